// round 2
// baseline (speedup 1.0000x reference)
#include <cuda_runtime.h>
#include <cuda_bf16.h>
#include <mma.h>
#include <cstdint>

using namespace nvcuda;

// ---------------- problem constants ----------------
namespace cfg {
constexpr int Bb = 4, Ss = 2048, Mm = 4, Dd = 2048, Ee = 1024, Hh = 8, DPH = 128;
constexpr int T  = Bb * Ss;        // 8192 tokens
constexpr int Nn = Dd + Mm * Dd;   // 10240 = value(2048) + 4 key branches
constexpr int Kd = Ee;             // 1024 reduction dim
constexpr float EPS_GATE   = 1.1920929e-07f;
constexpr float EPS_CONV   = 1e-5f;
constexpr float INV_SQRT_D = 0.022097086912079612f;  // 1/sqrt(2048)
}

// cumulative offsets of PRIMES (excluding last)
__device__ const int64_t d_off[8] = {0, 130003, 260024, 390051, 520094, 650145, 780202, 910271};

// ---------------- scratch (__device__ globals: allocation-free rule) ----------------
__device__ __nv_bfloat16 g_emb[(size_t)cfg::T * cfg::Kd];            // 16 MB
__device__ __nv_bfloat16 g_W[(size_t)cfg::Nn * cfg::Kd];             // 20 MB
__device__ float         g_V[(size_t)cfg::T * cfg::Dd];              // 64 MB  value
__device__ float         g_K[(size_t)cfg::T * cfg::Mm * cfg::Dd];    // 256 MB keys
__device__ float         g_gate[cfg::T * cfg::Mm];
__device__ float         g_gr[cfg::T * cfg::Mm];                     // gate * rstd_conv

// ---------------- helpers ----------------
__device__ __forceinline__ float warpSum(float v) {
#pragma unroll
    for (int o = 16; o; o >>= 1) v += __shfl_xor_sync(0xffffffffu, v, o);
    return v;
}

__device__ __forceinline__ void store_bf16x4(__nv_bfloat16* dst, float4 f) {
    __nv_bfloat162 lo = __floats2bfloat162_rn(f.x, f.y);
    __nv_bfloat162 hi = __floats2bfloat162_rn(f.z, f.w);
    uint2 u;
    u.x = *reinterpret_cast<uint32_t*>(&lo);
    u.y = *reinterpret_cast<uint32_t*>(&hi);
    *reinterpret_cast<uint2*>(dst) = u;
}

__device__ __forceinline__ void cp16(void* smem, const void* gmem) {
    uint32_t s = (uint32_t)__cvta_generic_to_shared(smem);
    asm volatile("cp.async.cg.shared.global [%0], [%1], 16;" :: "r"(s), "l"(gmem));
}

// ---------------- K1: hashed-embedding gather + cast to bf16 ----------------
__global__ void k_gather(const int* __restrict__ hidx, const float* __restrict__ table) {
    using namespace cfg;
    int e4 = blockIdx.x * blockDim.x + threadIdx.x;       // one float4 per thread
    if (e4 >= T * Ee / 4) return;
    int tok = e4 >> 8;             // 256 float4 per token
    int r   = e4 & 255;
    int h   = r >> 5;              // 32 float4 per head
    int j   = r & 31;
    int64_t row = (int64_t)__ldg(&hidx[tok * Hh + h]) + d_off[h];
    float4 f = reinterpret_cast<const float4*>(table + row * DPH)[j];
    store_bf16x4(&g_emb[((size_t)tok << 10) + (h << 7) + (j << 2)], f);
}

// ---------------- K2: cast [w_v ; w_k] -> bf16 ----------------
__global__ void k_castW(const float* __restrict__ wv, const float* __restrict__ wk) {
    using namespace cfg;
    int i4 = blockIdx.x * blockDim.x + threadIdx.x;
    int total4 = Nn * Kd / 4;
    if (i4 >= total4) return;
    constexpr int split4 = Dd * Kd / 4;   // w_v covers rows [0,2048)
    float4 f = (i4 < split4) ? reinterpret_cast<const float4*>(wv)[i4]
                             : reinterpret_cast<const float4*>(wk)[i4 - split4];
    store_bf16x4(&g_W[(size_t)i4 * 4], f);
}

// ---------------- K3: bf16 WMMA GEMM; rows 0..2047 of W -> g_V, rest -> g_K ----------------
namespace gmm {
constexpr int BM = 128, BN = 128, BK = 32, PAD = 8, LDT = BK + PAD;
}

__global__ __launch_bounds__(256, 1) void k_gemm() {
    using namespace cfg;
    using namespace gmm;
    __shared__ alignas(16) __nv_bfloat16 As[2][BM * LDT];   // 10 KB each stage pair
    __shared__ alignas(16) __nv_bfloat16 Bs[2][BN * LDT];

    const int tid = threadIdx.x;
    const int wid = tid >> 5;
    const int wm  = wid & 3;       // warp m-offset = wm*32
    const int wn  = wid >> 2;      // warp n-offset = wn*64
    const int bm  = blockIdx.x * BM;
    const int bn  = blockIdx.y * BN;

    wmma::fragment<wmma::accumulator, 16, 16, 16, float> acc[2][4];
#pragma unroll
    for (int i = 0; i < 2; i++)
#pragma unroll
        for (int j = 0; j < 4; j++) wmma::fill_fragment(acc[i][j], 0.0f);

    auto load_tile = [&](int st, int kt) {
        const int k0 = kt * BK;
#pragma unroll
        for (int u = 0; u < 2; u++) {
            int c = tid + u * 256;                 // 512 chunks of 8 bf16
            int row = c >> 2, kc = (c & 3) << 3;
            cp16(&As[st][row * LDT + kc], g_emb + (size_t)(bm + row) * Kd + k0 + kc);
        }
#pragma unroll
        for (int u = 0; u < 2; u++) {
            int c = tid + u * 256;
            int row = c >> 2, kc = (c & 3) << 3;
            cp16(&Bs[st][row * LDT + kc], g_W + (size_t)(bn + row) * Kd + k0 + kc);
        }
        asm volatile("cp.async.commit_group;" ::: "memory");
    };

    load_tile(0, 0);
    constexpr int NKT = Kd / BK;   // 32
    for (int kt = 0; kt < NKT; kt++) {
        int cur = kt & 1;
        if (kt + 1 < NKT) {
            load_tile(cur ^ 1, kt + 1);
            asm volatile("cp.async.wait_group 1;" ::: "memory");
        } else {
            asm volatile("cp.async.wait_group 0;" ::: "memory");
        }
        __syncthreads();
#pragma unroll
        for (int ks = 0; ks < BK; ks += 16) {
            wmma::fragment<wmma::matrix_a, 16, 16, 16, __nv_bfloat16, wmma::row_major> af[2];
            wmma::fragment<wmma::matrix_b, 16, 16, 16, __nv_bfloat16, wmma::col_major> bf[4];
#pragma unroll
            for (int i = 0; i < 2; i++)
                wmma::load_matrix_sync(af[i], &As[cur][(wm * 32 + i * 16) * LDT + ks], LDT);
#pragma unroll
            for (int j = 0; j < 4; j++)
                wmma::load_matrix_sync(bf[j], &Bs[cur][(wn * 64 + j * 16) * LDT + ks], LDT);
#pragma unroll
            for (int i = 0; i < 2; i++)
#pragma unroll
                for (int j = 0; j < 4; j++)
                    wmma::mma_sync(acc[i][j], af[i], bf[j], acc[i][j]);
        }
        __syncthreads();
    }

    // epilogue: split into value / keys buffers (BN=128 never straddles the 2048 boundary)
#pragma unroll
    for (int i = 0; i < 2; i++)
#pragma unroll
        for (int j = 0; j < 4; j++) {
            int r = bm + wm * 32 + i * 16;
            int c = bn + wn * 64 + j * 16;
            if (c < Dd)
                wmma::store_matrix_sync(g_V + (size_t)r * Dd + c, acc[i][j], Dd,
                                        wmma::mem_row_major);
            else
                wmma::store_matrix_sync(g_K + (size_t)r * (Mm * Dd) + (c - Dd), acc[i][j],
                                        Mm * Dd, wmma::mem_row_major);
        }
}

// ---------------- K4: fused mean(value^2) + per-(t,m) gate/conv scale ----------------
__global__ __launch_bounds__(256) void k_gate(const float* __restrict__ hidden,
                                              const float* __restrict__ nkw,
                                              const float* __restrict__ nhw) {
    using namespace cfg;
    const int t = blockIdx.x;
    const float* v = g_V + (size_t)t * Dd;
    float sv2 = 0.f, sk2[4] = {}, sh2[4] = {}, skh[4] = {};
    for (int d = threadIdx.x; d < Dd; d += 256) {
        float vv = v[d];
        sv2 += vv * vv;
#pragma unroll
        for (int m = 0; m < 4; m++) {
            float kv = g_K[((size_t)t * Mm + m) * Dd + d];
            float hv = hidden[((size_t)t * Mm + m) * Dd + d];
            sk2[m] += kv * kv;
            sh2[m] += hv * hv;
            skh[m] += kv * hv * __ldg(&nkw[m * Dd + d]) * __ldg(&nhw[m * Dd + d]);
        }
    }
    __shared__ float red[13][8];
    __shared__ float fin[13];
    int lane = threadIdx.x & 31, w = threadIdx.x >> 5;
    float vals[13] = {sv2, sk2[0], sk2[1], sk2[2], sk2[3],
                      sh2[0], sh2[1], sh2[2], sh2[3],
                      skh[0], skh[1], skh[2], skh[3]};
#pragma unroll
    for (int i = 0; i < 13; i++) {
        float s = warpSum(vals[i]);
        if (lane == 0) red[i][w] = s;
    }
    __syncthreads();
    if (threadIdx.x < 13) {
        float tot = 0.f;
#pragma unroll
        for (int i = 0; i < 8; i++) tot += red[threadIdx.x][i];
        fin[threadIdx.x] = tot;
    }
    __syncthreads();
    if (threadIdx.x < 4) {
        int m = threadIdx.x;
        float meanv2 = fin[0] * (1.0f / Dd);
        float rk = rsqrtf(fin[1 + m] * (1.0f / Dd) + EPS_GATE);
        float rq = rsqrtf(fin[5 + m] * (1.0f / Dd) + EPS_GATE);
        float score = fin[9 + m] * rk * rq * INV_SQRT_D;
        float g = sqrtf(fmaxf(fabsf(score), 1e-6f));
        g = score > 0.f ? g : (score < 0.f ? -g : 0.f);
        float gate = 1.0f / (1.0f + expf(-g));
        float rstdc = rsqrtf(gate * gate * meanv2 + EPS_CONV);
        g_gate[t * Mm + m] = gate;
        g_gr[t * Mm + m]   = gate * rstdc;
    }
}

// ---------------- K5: dilated causal depthwise conv + SiLU + residual ----------------
__global__ __launch_bounds__(256) void k_out(const float* __restrict__ hidden,
                                             const float* __restrict__ cnw_,
                                             const float* __restrict__ convw,
                                             float* __restrict__ out) {
    using namespace cfg;
    const int t = blockIdx.x;
    const int s = t & (Ss - 1);                       // position in sequence (Ss power of 2)
    __shared__ float sv[4][Dd];                       // 4 tap rows of value, 32 KB
    __shared__ float sgr[4][Mm];                      // gr per tap,branch
    __shared__ float sgate[Mm];

    // stage value tap rows: tap k corresponds to time s-9+3k (k=3 is current token)
    for (int i = threadIdx.x; i < 4 * Dd; i += 256) {
        int k = i >> 11, d = i & (Dd - 1);
        int tau = s - 9 + 3 * k;
        sv[k][d] = (tau >= 0) ? g_V[(size_t)(t - 9 + 3 * k) * Dd + d] : 0.0f;
    }
    if (threadIdx.x < 16) {
        int k = threadIdx.x >> 2, m = threadIdx.x & 3;
        int tau = s - 9 + 3 * k;
        sgr[k][m] = (tau >= 0) ? g_gr[(t - 9 + 3 * k) * Mm + m] : 0.0f;
        if (k == 3) sgate[m] = g_gate[t * Mm + m];
    }
    __syncthreads();

    for (int i = threadIdx.x; i < Mm * Dd; i += 256) {
        int m = i >> 11, d = i & (Dd - 1);
        int c = m * Dd + d;
        float cn = __ldg(&cnw_[c]);
        float4 cw4 = __ldg(reinterpret_cast<const float4*>(convw + c * 4));
        float acc = cw4.x * (sgr[0][m] * sv[0][d])
                  + cw4.y * (sgr[1][m] * sv[1][d])
                  + cw4.z * (sgr[2][m] * sv[2][d])
                  + cw4.w * (sgr[3][m] * sv[3][d]);
        acc *= cn;
        float silu = acc / (1.0f + __expf(-acc));
        float gated = sgate[m] * sv[3][d];
        size_t o = ((size_t)t * Mm + m) * Dd + d;
        out[o] = hidden[o] + silu + gated;
    }
}

// ---------------- launch ----------------
extern "C" void kernel_launch(void* const* d_in, const int* in_sizes, int n_in,
                              void* d_out, int out_size) {
    (void)in_sizes; (void)n_in; (void)out_size;
    using namespace cfg;
    const int*   hidx   = (const int*)d_in[0];     // hash_indices [B,S,H] int32
    const float* hidden = (const float*)d_in[1];   // hidden_states [B,S,M,D]
    const float* table  = (const float*)d_in[2];   // emb_table [sum(PRIMES), DPH]
    const float* wv     = (const float*)d_in[3];   // w_v [D,E]
    const float* wk     = (const float*)d_in[4];   // w_k [M,D,E]
    const float* nhw    = (const float*)d_in[5];   // norm_h_w [M,D]
    const float* nkw    = (const float*)d_in[6];   // norm_k_w [M,D]
    const float* cnw    = (const float*)d_in[7];   // conv_norm_w [M,D]
    const float* cw     = (const float*)d_in[8];   // conv_w [M*D,K]
    float* out = (float*)d_out;

    {   // K1: gather
        int n4 = T * Ee / 4;
        k_gather<<<(n4 + 255) / 256, 256>>>(hidx, table);
    }
    {   // K2: weight cast
        int n4 = Nn * Kd / 4;
        k_castW<<<(n4 + 255) / 256, 256>>>(wv, wk);
    }
    {   // K3: GEMM
        dim3 grid(T / gmm::BM, Nn / gmm::BN);    // 64 x 80
        k_gemm<<<grid, 256>>>();
    }
    k_gate<<<T, 256>>>(hidden, nkw, nhw);
    k_out<<<T, 256>>>(hidden, cnw, cw, out);
}

// round 6
// speedup vs baseline: 1.3938x; 1.3938x over previous
#include <cuda_runtime.h>
#include <cuda_bf16.h>
#include <cstdint>

// ---------------- problem constants ----------------
namespace cfg {
constexpr int Bb = 4, Ss = 2048, Mm = 4, Dd = 2048, Ee = 1024, Hh = 8, DPH = 128;
constexpr int T  = Bb * Ss;        // 8192 tokens
constexpr int Nn = Dd + Mm * Dd;   // 10240
constexpr int Kd = Ee;             // 1024
constexpr float EPS_GATE   = 1.1920929e-07f;
constexpr float EPS_CONV   = 1e-5f;
constexpr float INV_SQRT_D = 0.022097086912079612f;
}

__device__ const int64_t d_off[8] = {0, 130003, 260024, 390051, 520094, 650145, 780202, 910271};

// ---------------- scratch ----------------
__device__ __nv_bfloat16 g_emb[(size_t)cfg::T * cfg::Kd];              // 16 MB
__device__ __nv_bfloat16 g_W[(size_t)cfg::Nn * cfg::Kd];               // 20 MB
__device__ float         g_V[(size_t)cfg::T * cfg::Dd];                // 64 MB  value fp32
__device__ __nv_bfloat16 g_Kb[(size_t)cfg::T * cfg::Mm * cfg::Dd];     // 128 MB keys bf16
__device__ float         g_gate[cfg::T * cfg::Mm];
__device__ float         g_gr[cfg::T * cfg::Mm];

// ---------------- helpers ----------------
__device__ __forceinline__ uint32_t smem_u32(const void* p) {
    uint32_t a;
    asm("{ .reg .u64 t; cvta.to.shared.u64 t, %1; cvt.u32.u64 %0, t; }" : "=r"(a) : "l"(p));
    return a;
}
__device__ __forceinline__ void cp16s(uint32_t s, const void* g) {
    asm volatile("cp.async.cg.shared.global [%0], [%1], 16;" :: "r"(s), "l"(g));
}
#define SMEM_SWZ128(b) ((b) ^ (((b) >> 3) & 0x70))

__device__ __forceinline__ void ldmx4(uint32_t& r0, uint32_t& r1, uint32_t& r2, uint32_t& r3,
                                      uint32_t addr) {
    asm volatile("ldmatrix.sync.aligned.m8n8.x4.shared.b16 {%0,%1,%2,%3}, [%4];"
                 : "=r"(r0), "=r"(r1), "=r"(r2), "=r"(r3) : "r"(addr));
}
__device__ __forceinline__ void mma16816(float* c, uint32_t a0, uint32_t a1, uint32_t a2,
                                         uint32_t a3, uint32_t b0, uint32_t b1) {
    asm volatile("mma.sync.aligned.m16n8k16.row.col.f32.bf16.bf16.f32 "
                 "{%0,%1,%2,%3}, {%4,%5,%6,%7}, {%8,%9}, {%0,%1,%2,%3};"
                 : "+f"(c[0]), "+f"(c[1]), "+f"(c[2]), "+f"(c[3])
                 : "r"(a0), "r"(a1), "r"(a2), "r"(a3), "r"(b0), "r"(b1));
}
__device__ __forceinline__ float warpSum(float v) {
#pragma unroll
    for (int o = 16; o; o >>= 1) v += __shfl_xor_sync(0xffffffffu, v, o);
    return v;
}
__device__ __forceinline__ void store_bf16x4(__nv_bfloat16* dst, float4 f) {
    __nv_bfloat162 lo = __floats2bfloat162_rn(f.x, f.y);
    __nv_bfloat162 hi = __floats2bfloat162_rn(f.z, f.w);
    uint2 u;
    u.x = *reinterpret_cast<uint32_t*>(&lo);
    u.y = *reinterpret_cast<uint32_t*>(&hi);
    *reinterpret_cast<uint2*>(dst) = u;
}

// ---------------- K1: gather ----------------
__global__ void k_gather(const int* __restrict__ hidx, const float* __restrict__ table) {
    using namespace cfg;
    int e4 = blockIdx.x * blockDim.x + threadIdx.x;
    if (e4 >= T * Ee / 4) return;
    int tok = e4 >> 8, r = e4 & 255, h = r >> 5, j = r & 31;
    int64_t row = (int64_t)__ldg(&hidx[tok * Hh + h]) + d_off[h];
    float4 f = reinterpret_cast<const float4*>(table + row * DPH)[j];
    store_bf16x4(&g_emb[((size_t)tok << 10) + (h << 7) + (j << 2)], f);
}

// ---------------- K2: weight cast ----------------
__global__ void k_castW(const float* __restrict__ wv, const float* __restrict__ wk) {
    using namespace cfg;
    int i4 = blockIdx.x * blockDim.x + threadIdx.x;
    if (i4 >= Nn * Kd / 4) return;
    constexpr int split4 = Dd * Kd / 4;
    float4 f = (i4 < split4) ? reinterpret_cast<const float4*>(wv)[i4]
                             : reinterpret_cast<const float4*>(wk)[i4 - split4];
    store_bf16x4(&g_W[(size_t)i4 * 4], f);
}

// ---------------- K3: mma.sync bf16 GEMM, 128x128x64, 3-stage cp.async ----------------
namespace mm {
constexpr int BM = 128, BN = 128, BK = 64, NSTG = 3;
constexpr int NK = cfg::Kd / BK;               // 16
constexpr int ABYTES = BM * 128;               // 16 KB (128 rows x 128B)
constexpr int BBYTES = BN * 128;               // 16 KB
constexpr int SMEM_BYTES = NSTG * (ABYTES + BBYTES);   // 96 KB
}

__global__ __launch_bounds__(256, 1) void k_gemm_mma() {
    using namespace cfg;
    using namespace mm;
    extern __shared__ __align__(128) char dsm[];
    const uint32_t sbase = smem_u32(dsm);
    const uint32_t A0 = sbase, B0 = sbase + NSTG * ABYTES;
    const int tid = threadIdx.x, lane = tid & 31, wid = tid >> 5;
    const int wm = wid & 3, wn = wid >> 2;           // warp tile: 32 (m) x 64 (n)
    const int bm = blockIdx.x * BM, bn = blockIdx.y * BN;

    float acc[2][8][4];
#pragma unroll
    for (int i = 0; i < 2; i++)
#pragma unroll
        for (int j = 0; j < 8; j++)
#pragma unroll
            for (int q = 0; q < 4; q++) acc[i][j][q] = 0.0f;

    auto load_chunk = [&](int s, int c) {
        const int k0 = c * BK;                        // in elements
#pragma unroll
        for (int u = 0; u < 4; u++) {                 // A: 1024 chunks of 16B
            int idx = tid + u * 256;
            int row = idx >> 3, ui = idx & 7;
            cp16s(A0 + s * ABYTES + SMEM_SWZ128(row * 128 + ui * 16),
                  g_emb + (size_t)(bm + row) * Kd + k0 + ui * 8);
        }
#pragma unroll
        for (int u = 0; u < 4; u++) {                 // B: 1024 chunks of 16B
            int idx = tid + u * 256;
            int row = idx >> 3, ui = idx & 7;
            cp16s(B0 + s * BBYTES + SMEM_SWZ128(row * 128 + ui * 16),
                  g_W + (size_t)(bn + row) * Kd + k0 + ui * 8);
        }
        asm volatile("cp.async.commit_group;" ::: "memory");
    };

    // ldmatrix per-lane byte offsets (within a stage tile of 128B rows)
    // A tile (16x16 at row R0, col k0): lane l -> row R0 + l%8 + ((l>>3)&1)*8, col k0 + (l>>4)*8
    const int a_r = (lane & 7) + ((lane >> 3) & 1) * 8;
    const int a_c2 = (lane >> 4) * 16;                // byte offset of col half
    // B tile (two n8 tiles at N0, col k0): lane l -> row N0 + (l>>4)*8 + l%8, col k0 + ((l>>3)&1)*8
    const int b_r = (lane >> 4) * 8 + (lane & 7);
    const int b_c2 = ((lane >> 3) & 1) * 16;

    load_chunk(0, 0);
    load_chunk(1, 1);

    for (int c = 0; c < NK; c++) {
        const int s = c % NSTG;
        const int rem = NK - 1 - c;
        if (rem >= 1) asm volatile("cp.async.wait_group 1;" ::: "memory");
        else          asm volatile("cp.async.wait_group 0;" ::: "memory");
        __syncthreads();
        if (c + 2 < NK) load_chunk((c + 2) % NSTG, c + 2);

        const uint32_t abase = A0 + s * ABYTES;
        const uint32_t bbase = B0 + s * BBYTES;
#pragma unroll
        for (int ks = 0; ks < BK / 16; ks++) {
            const int k0b = ks * 32;                  // byte offset of k0
            uint32_t a[2][4];
#pragma unroll
            for (int mt = 0; mt < 2; mt++) {
                int row = wm * 32 + mt * 16 + a_r;
                ldmx4(a[mt][0], a[mt][1], a[mt][2], a[mt][3],
                      abase + SMEM_SWZ128(row * 128 + k0b + a_c2));
            }
            uint32_t b[8][2];
#pragma unroll
            for (int np = 0; np < 4; np++) {          // pairs of n8 tiles
                int row = wn * 64 + np * 16 + b_r;
                ldmx4(b[np * 2][0], b[np * 2][1], b[np * 2 + 1][0], b[np * 2 + 1][1],
                      bbase + SMEM_SWZ128(row * 128 + k0b + b_c2));
            }
#pragma unroll
            for (int mt = 0; mt < 2; mt++)
#pragma unroll
                for (int nt = 0; nt < 8; nt++)
                    mma16816(acc[mt][nt], a[mt][0], a[mt][1], a[mt][2], a[mt][3],
                             b[nt][0], b[nt][1]);
        }
    }

    // epilogue: c regs {0,1} -> row r0, cols col,col+1; {2,3} -> row r0+8
    const int er = lane >> 2, ec = (lane & 3) * 2;
    if (bn < Dd) {
#pragma unroll
        for (int mt = 0; mt < 2; mt++)
#pragma unroll
            for (int nt = 0; nt < 8; nt++) {
                int r = bm + wm * 32 + mt * 16 + er;
                int col = bn + wn * 64 + nt * 8 + ec;
                *reinterpret_cast<float2*>(g_V + (size_t)r * Dd + col) =
                    make_float2(acc[mt][nt][0], acc[mt][nt][1]);
                *reinterpret_cast<float2*>(g_V + (size_t)(r + 8) * Dd + col) =
                    make_float2(acc[mt][nt][2], acc[mt][nt][3]);
            }
    } else {
#pragma unroll
        for (int mt = 0; mt < 2; mt++)
#pragma unroll
            for (int nt = 0; nt < 8; nt++) {
                int r = bm + wm * 32 + mt * 16 + er;
                int col = bn - Dd + wn * 64 + nt * 8 + ec;
                __nv_bfloat162 lo = __floats2bfloat162_rn(acc[mt][nt][0], acc[mt][nt][1]);
                __nv_bfloat162 hi = __floats2bfloat162_rn(acc[mt][nt][2], acc[mt][nt][3]);
                *reinterpret_cast<uint32_t*>(g_Kb + (size_t)r * (Mm * Dd) + col) =
                    *reinterpret_cast<uint32_t*>(&lo);
                *reinterpret_cast<uint32_t*>(g_Kb + (size_t)(r + 8) * (Mm * Dd) + col) =
                    *reinterpret_cast<uint32_t*>(&hi);
            }
    }
}

// ---------------- K4: fused mean(v^2) + gate (vectorized) ----------------
__global__ __launch_bounds__(256) void k_gate(const float* __restrict__ hidden,
                                              const float* __restrict__ nkw,
                                              const float* __restrict__ nhw) {
    using namespace cfg;
    const int t = blockIdx.x;
    const float* v = g_V + (size_t)t * Dd;
    float sv2 = 0.f, sk2[4] = {}, sh2[4] = {}, skh[4] = {};
#pragma unroll
    for (int it = 0; it < 2; it++) {
        int d = threadIdx.x * 4 + it * 1024;
        float4 v4 = *reinterpret_cast<const float4*>(v + d);
        sv2 += v4.x * v4.x + v4.y * v4.y + v4.z * v4.z + v4.w * v4.w;
#pragma unroll
        for (int m = 0; m < 4; m++) {
            const size_t ro = ((size_t)t * Mm + m) * Dd + d;
            float4 h4 = *reinterpret_cast<const float4*>(hidden + ro);
            const __nv_bfloat162* kp = reinterpret_cast<const __nv_bfloat162*>(g_Kb + ro);
            float2 k01 = __bfloat1622float2(kp[0]);
            float2 k23 = __bfloat1622float2(kp[1]);
            float4 wk4 = __ldg(reinterpret_cast<const float4*>(nkw + m * Dd + d));
            float4 wh4 = __ldg(reinterpret_cast<const float4*>(nhw + m * Dd + d));
            sk2[m] += k01.x * k01.x + k01.y * k01.y + k23.x * k23.x + k23.y * k23.y;
            sh2[m] += h4.x * h4.x + h4.y * h4.y + h4.z * h4.z + h4.w * h4.w;
            skh[m] += k01.x * h4.x * wk4.x * wh4.x + k01.y * h4.y * wk4.y * wh4.y
                    + k23.x * h4.z * wk4.z * wh4.z + k23.y * h4.w * wk4.w * wh4.w;
        }
    }
    __shared__ float red[13][8], fin[13];
    int lane = threadIdx.x & 31, w = threadIdx.x >> 5;
    float vals[13] = {sv2, sk2[0], sk2[1], sk2[2], sk2[3], sh2[0], sh2[1], sh2[2], sh2[3],
                      skh[0], skh[1], skh[2], skh[3]};
#pragma unroll
    for (int i = 0; i < 13; i++) {
        float s = warpSum(vals[i]);
        if (lane == 0) red[i][w] = s;
    }
    __syncthreads();
    if (threadIdx.x < 13) {
        float tot = 0.f;
#pragma unroll
        for (int i = 0; i < 8; i++) tot += red[threadIdx.x][i];
        fin[threadIdx.x] = tot;
    }
    __syncthreads();
    if (threadIdx.x < 4) {
        int m = threadIdx.x;
        float meanv2 = fin[0] * (1.0f / Dd);
        float rk = rsqrtf(fin[1 + m] * (1.0f / Dd) + EPS_GATE);
        float rq = rsqrtf(fin[5 + m] * (1.0f / Dd) + EPS_GATE);
        float score = fin[9 + m] * rk * rq * INV_SQRT_D;
        float g = sqrtf(fmaxf(fabsf(score), 1e-6f));
        g = score > 0.f ? g : (score < 0.f ? -g : 0.f);
        float gate = 1.0f / (1.0f + expf(-g));
        float rstdc = rsqrtf(gate * gate * meanv2 + EPS_CONV);
        g_gate[t * Mm + m] = gate;
        g_gr[t * Mm + m]   = gate * rstdc;
    }
}

// ---------------- K5: conv + SiLU + residual ----------------
__global__ __launch_bounds__(256) void k_out(const float* __restrict__ hidden,
                                             const float* __restrict__ cnw_,
                                             const float* __restrict__ convw,
                                             float* __restrict__ out) {
    using namespace cfg;
    const int t = blockIdx.x;
    const int s = t & (Ss - 1);
    __shared__ float sv[4][Dd];
    __shared__ float sgr[4][Mm];
    __shared__ float sgate[Mm];
    for (int i = threadIdx.x; i < 4 * Dd; i += 256) {
        int k = i >> 11, d = i & (Dd - 1);
        int tau = s - 9 + 3 * k;
        sv[k][d] = (tau >= 0) ? g_V[(size_t)(t - 9 + 3 * k) * Dd + d] : 0.0f;
    }
    if (threadIdx.x < 16) {
        int k = threadIdx.x >> 2, m = threadIdx.x & 3;
        int tau = s - 9 + 3 * k;
        sgr[k][m] = (tau >= 0) ? g_gr[(t - 9 + 3 * k) * Mm + m] : 0.0f;
        if (k == 3) sgate[m] = g_gate[t * Mm + m];
    }
    __syncthreads();
    for (int i = threadIdx.x; i < Mm * Dd; i += 256) {
        int m = i >> 11, d = i & (Dd - 1);
        int c = m * Dd + d;
        float cn = __ldg(&cnw_[c]);
        float4 cw4 = __ldg(reinterpret_cast<const float4*>(convw + c * 4));
        float acc = cw4.x * (sgr[0][m] * sv[0][d]) + cw4.y * (sgr[1][m] * sv[1][d])
                  + cw4.z * (sgr[2][m] * sv[2][d]) + cw4.w * (sgr[3][m] * sv[3][d]);
        acc *= cn;
        float silu = acc / (1.0f + __expf(-acc));
        float gated = sgate[m] * sv[3][d];
        size_t o = ((size_t)t * Mm + m) * Dd + d;
        out[o] = hidden[o] + silu + gated;
    }
}

// ---------------- launch ----------------
extern "C" void kernel_launch(void* const* d_in, const int* in_sizes, int n_in,
                              void* d_out, int out_size) {
    (void)in_sizes; (void)n_in; (void)out_size;
    using namespace cfg;
    const int*   hidx   = (const int*)d_in[0];
    const float* hidden = (const float*)d_in[1];
    const float* table  = (const float*)d_in[2];
    const float* wv     = (const float*)d_in[3];
    const float* wk     = (const float*)d_in[4];
    const float* nhw    = (const float*)d_in[5];
    const float* nkw    = (const float*)d_in[6];
    const float* cnw    = (const float*)d_in[7];
    const float* cw     = (const float*)d_in[8];
    float* out = (float*)d_out;

    cudaFuncSetAttribute(k_gemm_mma, cudaFuncAttributeMaxDynamicSharedMemorySize,
                         mm::SMEM_BYTES);

    { int n4 = T * Ee / 4; k_gather<<<(n4 + 255) / 256, 256>>>(hidx, table); }
    { int n4 = Nn * Kd / 4; k_castW<<<(n4 + 255) / 256, 256>>>(wv, wk); }
    { dim3 grid(T / mm::BM, Nn / mm::BN); k_gemm_mma<<<grid, 256, mm::SMEM_BYTES>>>(); }
    k_gate<<<T, 256>>>(hidden, nkw, nhw);
    k_out<<<T, 256>>>(hidden, cnw, cw, out);
}

// round 9
// speedup vs baseline: 1.5186x; 1.0896x over previous
#include <cuda_runtime.h>
#include <cuda_bf16.h>
#include <cstdint>

// ---------------- problem constants ----------------
namespace cfg {
constexpr int Bb = 4, Ss = 2048, Mm = 4, Dd = 2048, Ee = 1024, Hh = 8, DPH = 128;
constexpr int T  = Bb * Ss;        // 8192 tokens
constexpr int Nn = Dd + Mm * Dd;   // 10240
constexpr int Kd = Ee;             // 1024
constexpr float EPS_GATE   = 1.1920929e-07f;
constexpr float EPS_CONV   = 1e-5f;
constexpr float INV_SQRT_D = 0.022097086912079612f;
}

__device__ const int64_t d_off[8] = {0, 130003, 260024, 390051, 520094, 650145, 780202, 910271};

// ---------------- scratch ----------------
__device__ __nv_bfloat16 g_emb[(size_t)cfg::T * cfg::Kd];              // 16 MB
__device__ __nv_bfloat16 g_W[(size_t)cfg::Nn * cfg::Kd];               // 20 MB
__device__ __nv_bfloat16 g_Vb[(size_t)cfg::T * cfg::Dd];               // 32 MB  value bf16
__device__ __nv_bfloat16 g_Kb[(size_t)cfg::T * cfg::Mm * cfg::Dd];     // 128 MB keys bf16
__device__ float         g_gate[cfg::T * cfg::Mm];
__device__ float         g_gr[cfg::T * cfg::Mm];

// ---------------- helpers ----------------
__device__ __forceinline__ uint32_t smem_u32(const void* p) {
    uint32_t a;
    asm("{ .reg .u64 t; cvta.to.shared.u64 t, %1; cvt.u32.u64 %0, t; }" : "=r"(a) : "l"(p));
    return a;
}
__device__ __forceinline__ void cp16s(uint32_t s, const void* g) {
    asm volatile("cp.async.cg.shared.global [%0], [%1], 16;" :: "r"(s), "l"(g));
}
#define SMEM_SWZ128(b) ((b) ^ (((b) >> 3) & 0x70))

__device__ __forceinline__ void ldmx4(uint32_t& r0, uint32_t& r1, uint32_t& r2, uint32_t& r3,
                                      uint32_t addr) {
    asm volatile("ldmatrix.sync.aligned.m8n8.x4.shared.b16 {%0,%1,%2,%3}, [%4];"
                 : "=r"(r0), "=r"(r1), "=r"(r2), "=r"(r3) : "r"(addr));
}
__device__ __forceinline__ void mma16816(float* c, uint32_t a0, uint32_t a1, uint32_t a2,
                                         uint32_t a3, uint32_t b0, uint32_t b1) {
    asm volatile("mma.sync.aligned.m16n8k16.row.col.f32.bf16.bf16.f32 "
                 "{%0,%1,%2,%3}, {%4,%5,%6,%7}, {%8,%9}, {%0,%1,%2,%3};"
                 : "+f"(c[0]), "+f"(c[1]), "+f"(c[2]), "+f"(c[3])
                 : "r"(a0), "r"(a1), "r"(a2), "r"(a3), "r"(b0), "r"(b1));
}
__device__ __forceinline__ float warpSum(float v) {
#pragma unroll
    for (int o = 16; o; o >>= 1) v += __shfl_xor_sync(0xffffffffu, v, o);
    return v;
}
__device__ __forceinline__ void store_bf16x4(__nv_bfloat16* dst, float4 f) {
    __nv_bfloat162 lo = __floats2bfloat162_rn(f.x, f.y);
    __nv_bfloat162 hi = __floats2bfloat162_rn(f.z, f.w);
    uint2 u;
    u.x = *reinterpret_cast<uint32_t*>(&lo);
    u.y = *reinterpret_cast<uint32_t*>(&hi);
    *reinterpret_cast<uint2*>(dst) = u;
}

// ---------------- K1: gather ----------------
__global__ void k_gather(const int* __restrict__ hidx, const float* __restrict__ table) {
    using namespace cfg;
    int e4 = blockIdx.x * blockDim.x + threadIdx.x;
    if (e4 >= T * Ee / 4) return;
    int tok = e4 >> 8, r = e4 & 255, h = r >> 5, j = r & 31;
    int64_t row = (int64_t)__ldg(&hidx[tok * Hh + h]) + d_off[h];
    float4 f = reinterpret_cast<const float4*>(table + row * DPH)[j];
    store_bf16x4(&g_emb[((size_t)tok << 10) + (h << 7) + (j << 2)], f);
}

// ---------------- K2: weight cast ----------------
__global__ void k_castW(const float* __restrict__ wv, const float* __restrict__ wk) {
    using namespace cfg;
    int i4 = blockIdx.x * blockDim.x + threadIdx.x;
    if (i4 >= Nn * Kd / 4) return;
    constexpr int split4 = Dd * Kd / 4;
    float4 f = (i4 < split4) ? reinterpret_cast<const float4*>(wv)[i4]
                             : reinterpret_cast<const float4*>(wk)[i4 - split4];
    store_bf16x4(&g_W[(size_t)i4 * 4], f);
}

// ---------------- K3: mma.sync bf16 GEMM, 128x256x64, warp tile 64x64, 3-stage ----------------
namespace mm {
constexpr int BM = 128, BN = 256, BK = 64, NSTG = 3;
constexpr int NK = cfg::Kd / BK;               // 16
constexpr int ABYTES = BM * 128;               // 16 KB / stage
constexpr int BBYTES = BN * 128;               // 32 KB / stage
constexpr int SMEM_BYTES = NSTG * (ABYTES + BBYTES);   // 144 KB
}

__global__ __launch_bounds__(256, 1) void k_gemm_mma() {
    using namespace cfg;
    using namespace mm;
    extern __shared__ __align__(128) char dsm[];
    const uint32_t sbase = smem_u32(dsm);
    const uint32_t A0 = sbase, B0 = sbase + NSTG * ABYTES;
    const int tid = threadIdx.x, lane = tid & 31, wid = tid >> 5;
    const int wm = wid & 1, wn = wid >> 1;           // warp tile: 64 (m) x 64 (n)
    const int bm = blockIdx.x * BM, bn = blockIdx.y * BN;

    float acc[4][8][4];
#pragma unroll
    for (int i = 0; i < 4; i++)
#pragma unroll
        for (int j = 0; j < 8; j++)
#pragma unroll
            for (int q = 0; q < 4; q++) acc[i][j][q] = 0.0f;

    auto load_chunk = [&](int s, int c) {
        const int k0 = c * BK;                        // elements
#pragma unroll
        for (int u = 0; u < 4; u++) {                 // A: 1024 x 16B
            int idx = tid + u * 256;
            int row = idx >> 3, ui = idx & 7;
            cp16s(A0 + s * ABYTES + SMEM_SWZ128(row * 128 + ui * 16),
                  g_emb + (size_t)(bm + row) * Kd + k0 + ui * 8);
        }
#pragma unroll
        for (int u = 0; u < 8; u++) {                 // B: 2048 x 16B
            int idx = tid + u * 256;
            int row = idx >> 3, ui = idx & 7;
            cp16s(B0 + s * BBYTES + SMEM_SWZ128(row * 128 + ui * 16),
                  g_W + (size_t)(bn + row) * Kd + k0 + ui * 8);
        }
        asm volatile("cp.async.commit_group;" ::: "memory");
    };

    // ldmatrix lane address components
    const int a_r = (lane & 7) + ((lane >> 3) & 1) * 8;   // A m16k16 tile
    const int a_c2 = (lane >> 4) * 16;
    const int b_r = (lane >> 4) * 8 + (lane & 7);          // B two-n8 tile
    const int b_c2 = ((lane >> 3) & 1) * 16;

    load_chunk(0, 0);
    load_chunk(1, 1);

    for (int c = 0; c < NK; c++) {
        const int s = c % NSTG;
        const int rem = NK - 1 - c;
        if (rem >= 1) asm volatile("cp.async.wait_group 1;" ::: "memory");
        else          asm volatile("cp.async.wait_group 0;" ::: "memory");
        __syncthreads();
        if (c + 2 < NK) load_chunk((c + 2) % NSTG, c + 2);

        const uint32_t abase = A0 + s * ABYTES;
        const uint32_t bbase = B0 + s * BBYTES;
#pragma unroll
        for (int ks = 0; ks < BK / 16; ks++) {
            const int k0b = ks * 32;
            uint32_t a[4][4];
#pragma unroll
            for (int mt = 0; mt < 4; mt++) {
                int row = wm * 64 + mt * 16 + a_r;
                ldmx4(a[mt][0], a[mt][1], a[mt][2], a[mt][3],
                      abase + SMEM_SWZ128(row * 128 + k0b + a_c2));
            }
            uint32_t b[8][2];
#pragma unroll
            for (int np = 0; np < 4; np++) {
                int row = wn * 64 + np * 16 + b_r;
                ldmx4(b[np * 2][0], b[np * 2][1], b[np * 2 + 1][0], b[np * 2 + 1][1],
                      bbase + SMEM_SWZ128(row * 128 + k0b + b_c2));
            }
#pragma unroll
            for (int mt = 0; mt < 4; mt++)
#pragma unroll
                for (int nt = 0; nt < 8; nt++)
                    mma16816(acc[mt][nt], a[mt][0], a[mt][1], a[mt][2], a[mt][3],
                             b[nt][0], b[nt][1]);
        }
    }

    // epilogue: all tiles -> bf16 (value or key buffer; BN=256 never straddles boundary)
    const int er = lane >> 2, ec = (lane & 3) * 2;
    const bool isV = (bn < Dd);
#pragma unroll
    for (int mt = 0; mt < 4; mt++)
#pragma unroll
        for (int nt = 0; nt < 8; nt++) {
            int r = bm + wm * 64 + mt * 16 + er;
            int col = wn * 64 + nt * 8 + ec;
            __nv_bfloat16* dst;
            if (isV) dst = g_Vb + (size_t)r * Dd + bn + col;
            else     dst = g_Kb + (size_t)r * (Mm * Dd) + (bn - Dd) + col;
            __nv_bfloat162 lo = __floats2bfloat162_rn(acc[mt][nt][0], acc[mt][nt][1]);
            __nv_bfloat162 hi = __floats2bfloat162_rn(acc[mt][nt][2], acc[mt][nt][3]);
            *reinterpret_cast<uint32_t*>(dst) = *reinterpret_cast<uint32_t*>(&lo);
            *reinterpret_cast<uint32_t*>(dst + (isV ? Dd : Mm * Dd) * 8) =
                *reinterpret_cast<uint32_t*>(&hi);
        }
}

// ---------------- K4: fused mean(v^2) + gate ----------------
__global__ __launch_bounds__(256) void k_gate(const float* __restrict__ hidden,
                                              const float* __restrict__ nkw,
                                              const float* __restrict__ nhw) {
    using namespace cfg;
    const int t = blockIdx.x;
    const __nv_bfloat16* v = g_Vb + (size_t)t * Dd;
    float sv2 = 0.f, sk2[4] = {}, sh2[4] = {}, skh[4] = {};
#pragma unroll
    for (int it = 0; it < 2; it++) {
        int d = threadIdx.x * 4 + it * 1024;
        const __nv_bfloat162* vp = reinterpret_cast<const __nv_bfloat162*>(v + d);
        float2 v01 = __bfloat1622float2(vp[0]);
        float2 v23 = __bfloat1622float2(vp[1]);
        sv2 += v01.x * v01.x + v01.y * v01.y + v23.x * v23.x + v23.y * v23.y;
#pragma unroll
        for (int m = 0; m < 4; m++) {
            const size_t ro = ((size_t)t * Mm + m) * Dd + d;
            float4 h4 = *reinterpret_cast<const float4*>(hidden + ro);
            const __nv_bfloat162* kp = reinterpret_cast<const __nv_bfloat162*>(g_Kb + ro);
            float2 k01 = __bfloat1622float2(kp[0]);
            float2 k23 = __bfloat1622float2(kp[1]);
            float4 wk4 = __ldg(reinterpret_cast<const float4*>(nkw + m * Dd + d));
            float4 wh4 = __ldg(reinterpret_cast<const float4*>(nhw + m * Dd + d));
            sk2[m] += k01.x * k01.x + k01.y * k01.y + k23.x * k23.x + k23.y * k23.y;
            sh2[m] += h4.x * h4.x + h4.y * h4.y + h4.z * h4.z + h4.w * h4.w;
            skh[m] += k01.x * h4.x * wk4.x * wh4.x + k01.y * h4.y * wk4.y * wh4.y
                    + k23.x * h4.z * wk4.z * wh4.z + k23.y * h4.w * wk4.w * wh4.w;
        }
    }
    __shared__ float red[13][8], fin[13];
    int lane = threadIdx.x & 31, w = threadIdx.x >> 5;
    float vals[13] = {sv2, sk2[0], sk2[1], sk2[2], sk2[3], sh2[0], sh2[1], sh2[2], sh2[3],
                      skh[0], skh[1], skh[2], skh[3]};
#pragma unroll
    for (int i = 0; i < 13; i++) {
        float s = warpSum(vals[i]);
        if (lane == 0) red[i][w] = s;
    }
    __syncthreads();
    if (threadIdx.x < 13) {
        float tot = 0.f;
#pragma unroll
        for (int i = 0; i < 8; i++) tot += red[threadIdx.x][i];
        fin[threadIdx.x] = tot;
    }
    __syncthreads();
    if (threadIdx.x < 4) {
        int m = threadIdx.x;
        float meanv2 = fin[0] * (1.0f / Dd);
        float rk = rsqrtf(fin[1 + m] * (1.0f / Dd) + EPS_GATE);
        float rq = rsqrtf(fin[5 + m] * (1.0f / Dd) + EPS_GATE);
        float score = fin[9 + m] * rk * rq * INV_SQRT_D;
        float g = sqrtf(fmaxf(fabsf(score), 1e-6f));
        g = score > 0.f ? g : (score < 0.f ? -g : 0.f);
        float gate = 1.0f / (1.0f + expf(-g));
        float rstdc = rsqrtf(gate * gate * meanv2 + EPS_CONV);
        g_gate[t * Mm + m] = gate;
        g_gr[t * Mm + m]   = gate * rstdc;
    }
}

// ---------------- K5: conv + SiLU + residual ----------------
__global__ __launch_bounds__(256) void k_out(const float* __restrict__ hidden,
                                             const float* __restrict__ cnw_,
                                             const float* __restrict__ convw,
                                             float* __restrict__ out) {
    using namespace cfg;
    const int t = blockIdx.x;
    const int s = t & (Ss - 1);
    __shared__ float sv[4][Dd];
    __shared__ float sgr[4][Mm];
    __shared__ float sgate[Mm];
    for (int i = threadIdx.x; i < 4 * Dd / 2; i += 256) {   // bf16x2 loads
        int k = i >> 10, d2 = i & (Dd / 2 - 1);
        int tau = s - 9 + 3 * k;
        float2 f = make_float2(0.f, 0.f);
        if (tau >= 0) {
            __nv_bfloat162 h = *reinterpret_cast<const __nv_bfloat162*>(
                g_Vb + (size_t)(t - 9 + 3 * k) * Dd + d2 * 2);
            f = __bfloat1622float2(h);
        }
        sv[k][d2 * 2] = f.x;
        sv[k][d2 * 2 + 1] = f.y;
    }
    if (threadIdx.x < 16) {
        int k = threadIdx.x >> 2, m = threadIdx.x & 3;
        int tau = s - 9 + 3 * k;
        sgr[k][m] = (tau >= 0) ? g_gr[(t - 9 + 3 * k) * Mm + m] : 0.0f;
        if (k == 3) sgate[m] = g_gate[t * Mm + m];
    }
    __syncthreads();
    for (int i = threadIdx.x; i < Mm * Dd; i += 256) {
        int m = i >> 11, d = i & (Dd - 1);
        int c = m * Dd + d;
        float cn = __ldg(&cnw_[c]);
        float4 cw4 = __ldg(reinterpret_cast<const float4*>(convw + c * 4));
        float acc = cw4.x * (sgr[0][m] * sv[0][d]) + cw4.y * (sgr[1][m] * sv[1][d])
                  + cw4.z * (sgr[2][m] * sv[2][d]) + cw4.w * (sgr[3][m] * sv[3][d]);
        acc *= cn;
        float silu = acc / (1.0f + __expf(-acc));
        float gated = sgate[m] * sv[3][d];
        size_t o = ((size_t)t * Mm + m) * Dd + d;
        out[o] = hidden[o] + silu + gated;
    }
}

// ---------------- launch ----------------
extern "C" void kernel_launch(void* const* d_in, const int* in_sizes, int n_in,
                              void* d_out, int out_size) {
    (void)in_sizes; (void)n_in; (void)out_size;
    using namespace cfg;
    const int*   hidx   = (const int*)d_in[0];
    const float* hidden = (const float*)d_in[1];
    const float* table  = (const float*)d_in[2];
    const float* wv     = (const float*)d_in[3];
    const float* wk     = (const float*)d_in[4];
    const float* nhw    = (const float*)d_in[5];
    const float* nkw    = (const float*)d_in[6];
    const float* cnw    = (const float*)d_in[7];
    const float* cw     = (const float*)d_in[8];
    float* out = (float*)d_out;

    cudaFuncSetAttribute(k_gemm_mma, cudaFuncAttributeMaxDynamicSharedMemorySize,
                         mm::SMEM_BYTES);

    { int n4 = T * Ee / 4; k_gather<<<(n4 + 255) / 256, 256>>>(hidx, table); }
    { int n4 = Nn * Kd / 4; k_castW<<<(n4 + 255) / 256, 256>>>(wv, wk); }
    { dim3 grid(T / mm::BM, Nn / mm::BN); k_gemm_mma<<<grid, 256, mm::SMEM_BYTES>>>(); }
    k_gate<<<T, 256>>>(hidden, nkw, nhw);
    k_out<<<T, 256>>>(hidden, cnw, cw, out);
}